// round 7
// baseline (speedup 1.0000x reference)
#include <cuda_runtime.h>
#include <math.h>

#define INF_F 1000000000000.0f

typedef unsigned long long u64;

// ---------------- scratch (no cudaMalloc allowed) ----------------
__device__ float g_qw[16 * 512 * 64];    // rope'd q
__device__ float g_kw[16 * 512 * 64];    // rope'd k
__device__ float g_bq[16 * 12 * 512];    // bias[:,0::2]/2  (indexed by n)
__device__ float g_bk[16 * 12 * 512];    // bias[:,1::2]/2  (indexed by m)

// ---------------- f32x2 packed helpers (Blackwell FFMA2) ----------
__device__ __forceinline__ u64 pk2(float lo, float hi) {
    u64 r; asm("mov.b64 %0,{%1,%2};" : "=l"(r) : "f"(lo), "f"(hi)); return r;
}
__device__ __forceinline__ void fma2(u64 &c, u64 a, u64 b) {
    asm("fma.rn.f32x2 %0,%1,%2,%0;" : "+l"(c) : "l"(a), "l"(b));
}
__device__ __forceinline__ u64 add2(u64 a, u64 b) {
    u64 d; asm("add.rn.f32x2 %0,%1,%2;" : "=l"(d) : "l"(a), "l"(b)); return d;
}
__device__ __forceinline__ float2 up2(u64 v) {
    float2 f; asm("mov.b64 {%0,%1},%2;" : "=f"(f.x), "=f"(f.y) : "l"(v)); return f;
}

// ================= K1: x = inputs@W1+b1, rope split, bias =================
// Grid: 256 blocks (BM=32), 256 threads, BN=128 (full), BK=16.
// Microtile 4m x 4n: thread (tx=t&31, ty=t>>5), n0=tx*4, m0=ty*4.
// Per k-step: 1 broadcast LDS.128 (a) + 1 LDS.128 (b) + 4 packs + 8 FFMA2.
// Double-buffered smem, 1 sync/chunk. 8 warps/CTA -> 4 warps/SMSP at 2 CTA/SM.
__global__ void __launch_bounds__(256) k1_gemm(
    const float* __restrict__ inp, const float* __restrict__ W1,
    const float* __restrict__ b1v, const float* __restrict__ W2,
    const float* __restrict__ b2v)
{
    __shared__ __align__(16) float sm[7296];
    // main loop: 2 x (A[16][36]=576 + B[16][128]=2048) = 5248 fl
    // epilogue reuse: xS[32][132]=4224 + w2t[24][128]=3072 = 7296 fl

    int t = threadIdx.x;
    int tx = t & 31, ty = t >> 5;        // 32 x 8 thread grid
    int row0 = blockIdx.x * 32;
    int bidx = row0 >> 9;
    int pos0 = row0 & 511;
    int m0 = ty * 4, n0 = tx * 4;

    // A loader: float2 per thread (32 rows x 16 k = 512 fl / 256 thr)
    int am_ = t >> 3;                    // row 0..31
    int ak2 = (t & 7) << 1;              // k pair 0,2,..,14

    u64 acc[4][2];                       // [m][npair]
#pragma unroll
    for (int p = 0; p < 4; p++) { acc[p][0] = 0ULL; acc[p][1] = 0ULL; }

    float2 apre;
    float4 bpre[2];
    const float* arow = inp + (size_t)(row0 + am_) * 1024 + ak2;

    // ---- chunk 0 ----
    apre = *(const float2*)(arow);
#pragma unroll
    for (int i = 0; i < 2; i++) {
        int idx = t + i * 256; int k = idx >> 5; int n4 = (idx & 31) << 2;
        bpre[i] = *(const float4*)(W1 + (size_t)k * 128 + n4);
    }
    {
        float* aT = sm;
        float* bS = sm + 576;
        aT[(ak2 + 0) * 36 + am_] = apre.x;
        aT[(ak2 + 1) * 36 + am_] = apre.y;
#pragma unroll
        for (int i = 0; i < 2; i++) {
            int idx = t + i * 256; int k = idx >> 5; int n4 = (idx & 31) << 2;
            *(float4*)(bS + k * 128 + n4) = bpre[i];
        }
    }
    __syncthreads();

    for (int kc = 0; kc < 64; ++kc) {
        if (kc < 63) {
            int kb = (kc + 1) * 16;
            apre = *(const float2*)(arow + kb);
#pragma unroll
            for (int i = 0; i < 2; i++) {
                int idx = t + i * 256; int k = idx >> 5; int n4 = (idx & 31) << 2;
                bpre[i] = *(const float4*)(W1 + (size_t)(kb + k) * 128 + n4);
            }
        }
        const float* aT = sm + (kc & 1) * 2624;
        const float* bS = aT + 576;
#pragma unroll
        for (int k = 0; k < 16; k++) {
            float4 a = *(const float4*)(aT + k * 36 + m0);      // warp-broadcast
            const u64* bp = (const u64*)(bS + k * 128 + n0);
            u64 b0 = bp[0], b1 = bp[1];
            u64 a0 = pk2(a.x, a.x), a1 = pk2(a.y, a.y);
            u64 a2 = pk2(a.z, a.z), a3 = pk2(a.w, a.w);
            fma2(acc[0][0], a0, b0); fma2(acc[0][1], a0, b1);
            fma2(acc[1][0], a1, b0); fma2(acc[1][1], a1, b1);
            fma2(acc[2][0], a2, b0); fma2(acc[2][1], a2, b1);
            fma2(acc[3][0], a3, b0); fma2(acc[3][1], a3, b1);
        }
        if (kc < 63) {
            float* aTn = sm + ((kc + 1) & 1) * 2624;
            float* bSn = aTn + 576;
            aTn[(ak2 + 0) * 36 + am_] = apre.x;
            aTn[(ak2 + 1) * 36 + am_] = apre.y;
#pragma unroll
            for (int i = 0; i < 2; i++) {
                int idx = t + i * 256; int k = idx >> 5; int n4 = (idx & 31) << 2;
                *(float4*)(bSn + k * 128 + n4) = bpre[i];
            }
            __syncthreads();
        }
    }

    // ---- epilogue: unpack + b1 ----
    float x[4][4];
#pragma unroll
    for (int r = 0; r < 4; r++)
#pragma unroll
        for (int j = 0; j < 2; j++) {
            float2 v = up2(acc[r][j]);
            x[r][2 * j]     = v.x;
            x[r][2 * j + 1] = v.y;
        }
    float bc[4];
#pragma unroll
    for (int j = 0; j < 4; j++) bc[j] = __ldg(b1v + n0 + j);
#pragma unroll
    for (int r = 0; r < 4; r++)
#pragma unroll
        for (int j = 0; j < 4; j++) x[r][j] += bc[j];

    // ---- rope: this thread owns rope channel i = tx (cols 4tx..4tx+3) ----
    {
        float e = (float)(2 * tx) * (1.0f / 64.0f);
        float invf = 1.0f / powf(10000.0f, e);
#pragma unroll
        for (int r = 0; r < 4; r++) {
            int pos = pos0 + m0 + r;
            size_t rb = ((size_t)bidx * 512 + pos) * 64;
            float s, c;
            sincosf((float)pos * invf, &s, &c);
            float2 q = make_float2(x[r][0] * c - x[r][2] * s, x[r][0] * s + x[r][2] * c);
            float2 kk = make_float2(x[r][1] * c - x[r][3] * s, x[r][1] * s + x[r][3] * c);
            *(float2*)(g_qw + rb + 2 * tx) = q;
            *(float2*)(g_kw + rb + 2 * tx) = kk;
        }
    }

    // ---- bias: x @ W2 + b2, /2 ----
    __syncthreads();
    float* xS  = sm;             // [32][132]
    float* w2t = sm + 32 * 132;  // [24][128]
#pragma unroll
    for (int r = 0; r < 4; r++)
        *(float4*)(xS + (m0 + r) * 132 + n0) = make_float4(x[r][0], x[r][1], x[r][2], x[r][3]);
    for (int idx = t; idx < 3072; idx += 256) {
        int j = idx >> 7, k = idx & 127;
        w2t[j * 128 + k] = __ldg(W2 + k * 24 + j);
    }
    __syncthreads();

#pragma unroll
    for (int it = 0; it < 3; ++it) {
        int idx = t + it * 256;          // 768 (j,m) pairs
        int j = idx >> 5, m = idx & 31;
        const float* xr = xS + m * 132;
        const float* wr = w2t + j * 128;
        float s = 0.f;
#pragma unroll
        for (int k = 0; k < 128; k += 4) {
            float4 xv = *(const float4*)(xr + k);
            float4 wv = *(const float4*)(wr + k);
            s += xv.x * wv.x + xv.y * wv.y + xv.z * wv.z + xv.w * wv.w;
        }
        s = (s + __ldg(b2v + j)) * 0.5f;
        int pos = pos0 + m;
        int h = j >> 1;
        float* dst = (j & 1) ? g_bk : g_bq;
        dst[((size_t)bidx * 12 + h) * 512 + pos] = s;
    }
}

// ================= K2: qk + per-head epilogue + masks =================
// Grid (8 n-tiles, 8 m-tiles, 16 batches), 256 threads.
// Tile: 64m x 64n; microtile 4m x 4n. qk computed once (f32x2), 12-head fanout.
__global__ void __launch_bounds__(256) k2_out(const float* __restrict__ am,
                                              float* __restrict__ out)
{
    __shared__ __align__(16) float q_s[64 * 68];
    __shared__ __align__(16) float kT[64 * 64];
    __shared__ __align__(16) float bq_s[12 * 64];
    __shared__ __align__(16) float bk_s[12 * 64];
    __shared__ float amn_s[64];
    __shared__ float amm_s[64];

    int t = threadIdx.x;
    int b = blockIdx.z;
    int m0g = blockIdx.y * 64, n0g = blockIdx.x * 64;

#pragma unroll
    for (int i = 0; i < 4; i++) {
        int idx = t + i * 256;
        int row = idx >> 4, c = (idx & 15) << 2;
        *(float4*)(q_s + row * 68 + c) =
            *(const float4*)(g_qw + ((size_t)(b * 512 + m0g + row)) * 64 + c);
    }
    {
        int n = t & 63, kq = (t >> 6) << 4;
        const float* src = g_kw + ((size_t)(b * 512 + n0g + n)) * 64 + kq;
#pragma unroll
        for (int j = 0; j < 4; j++) {
            float4 v = *(const float4*)(src + j * 4);
            int kk = kq + j * 4;
            kT[(kk + 0) * 64 + n] = v.x;
            kT[(kk + 1) * 64 + n] = v.y;
            kT[(kk + 2) * 64 + n] = v.z;
            kT[(kk + 3) * 64 + n] = v.w;
        }
    }
#pragma unroll
    for (int i = 0; i < 3; i++) {
        int idx = t + i * 256;           // 768 entries each
        int h = idx >> 6, x = idx & 63;
        bq_s[idx] = g_bq[((size_t)b * 12 + h) * 512 + n0g + x];
        bk_s[idx] = g_bk[((size_t)b * 12 + h) * 512 + m0g + x];
    }
    if (t < 64)        amn_s[t]      = am[b * 512 + n0g + t];
    else if (t < 128)  amm_s[t - 64] = am[b * 512 + m0g + (t - 64)];
    __syncthreads();

    int tx = t & 15, ty = t >> 4;
    int n0 = tx * 4, m0 = ty * 4;

    // f32x2 qk accumulation: acc[m][npair]
    u64 acc[4][2];
#pragma unroll
    for (int r = 0; r < 4; r++) { acc[r][0] = 0ULL; acc[r][1] = 0ULL; }

#pragma unroll
    for (int k = 0; k < 64; k += 4) {
        float4 qr[4];
#pragma unroll
        for (int r = 0; r < 4; r++)
            qr[r] = *(const float4*)(q_s + (m0 + r) * 68 + k);
#pragma unroll
        for (int kk = 0; kk < 4; kk++) {
            const u64* kv = (const u64*)(kT + (k + kk) * 64 + n0);
            u64 k01 = kv[0], k23 = kv[1];
#pragma unroll
            for (int r = 0; r < 4; r++) {
                float qv = (kk == 0) ? qr[r].x : (kk == 1) ? qr[r].y
                         : (kk == 2) ? qr[r].z : qr[r].w;
                u64 qp = pk2(qv, qv);
                fma2(acc[r][0], k01, qp);
                fma2(acc[r][1], k23, qp);
            }
        }
    }

    float4 amn4 = *(const float4*)(amn_s + n0);
    float amn[4] = {amn4.x, amn4.y, amn4.z, amn4.w};
    int gn = n0g + n0;

    // pre = qk*0.125 - at - tr  (hoisted out of head loop; exact vs ref)
    u64 pre[4][2];
#pragma unroll
    for (int r = 0; r < 4; r++) {
        float am_m = amm_s[m0 + r];
        int gm = m0g + m0 + r;
        float2 vA = up2(acc[r][0]), vB = up2(acc[r][1]);
        float p[4] = {vA.x, vA.y, vB.x, vB.y};
        float pr[4];
#pragma unroll
        for (int j = 0; j < 4; j++) {
            float at = (1.0f - amn[j] * am_m) * INF_F;
            float tr = (gn + j < gm) ? INF_F : 0.f;
            pr[j] = p[j] * 0.125f - at - tr;
        }
        pre[r][0] = pk2(pr[0], pr[1]);
        pre[r][1] = pk2(pr[2], pr[3]);
    }

    float* obase = out + (((size_t)b * 12 * 512 + m0g + m0) * 512 + gn);
#pragma unroll
    for (int h = 0; h < 12; ++h) {
        const u64* bqp = (const u64*)(bq_s + h * 64 + n0);
        u64 bqa = bqp[0], bqb = bqp[1];
        float4 bk4 = *(const float4*)(bk_s + h * 64 + m0);
        float* oh = obase + (size_t)h * 512 * 512;
#pragma unroll
        for (int r = 0; r < 4; r++) {
            float bkv = (r == 0) ? bk4.x : (r == 1) ? bk4.y : (r == 2) ? bk4.z : bk4.w;
            u64 bkp = pk2(bkv, bkv);
            u64 wa = add2(add2(pre[r][0], bqa), bkp);
            u64 wb = add2(add2(pre[r][1], bqb), bkp);
            float2 lo = up2(wa), hi = up2(wb);
            __stcs((float4*)(oh + (size_t)r * 512), make_float4(lo.x, lo.y, hi.x, hi.y));
        }
    }
}

// ================= launch =================
extern "C" void kernel_launch(void* const* d_in, const int* in_sizes, int n_in,
                              void* d_out, int out_size)
{
    const float* inp = (const float*)d_in[0];
    const float* am  = (const float*)d_in[1];
    const float* W1  = (const float*)d_in[2];
    const float* b1  = (const float*)d_in[3];
    const float* W2  = (const float*)d_in[4];
    const float* b2  = (const float*)d_in[5];
    float* out = (float*)d_out;

    k1_gemm<<<256, 256>>>(inp, W1, b1, W2, b2);
    k2_out<<<dim3(8, 8, 16), 256>>>(am, out);
}

// round 8
// speedup vs baseline: 1.0202x; 1.0202x over previous
#include <cuda_runtime.h>
#include <math.h>

#define INF_F 1000000000000.0f

typedef unsigned long long u64;

// ---------------- scratch (no cudaMalloc allowed) ----------------
__device__ float g_qw[16 * 512 * 64];    // rope'd q
__device__ float g_kw[16 * 512 * 64];    // rope'd k
__device__ float g_bq[16 * 12 * 512];    // bias[:,0::2]/2  (indexed by n)
__device__ float g_bk[16 * 12 * 512];    // bias[:,1::2]/2  (indexed by m)

// ---------------- f32x2 packed helpers (Blackwell FFMA2) ----------
__device__ __forceinline__ u64 pk2(float lo, float hi) {
    u64 r; asm("mov.b64 %0,{%1,%2};" : "=l"(r) : "f"(lo), "f"(hi)); return r;
}
__device__ __forceinline__ void fma2(u64 &c, u64 a, u64 b) {
    asm("fma.rn.f32x2 %0,%1,%2,%0;" : "+l"(c) : "l"(a), "l"(b));
}
__device__ __forceinline__ u64 add2(u64 a, u64 b) {
    u64 d; asm("add.rn.f32x2 %0,%1,%2;" : "=l"(d) : "l"(a), "l"(b)); return d;
}
__device__ __forceinline__ float2 up2(u64 v) {
    float2 f; asm("mov.b64 {%0,%1},%2;" : "=f"(f.x), "=f"(f.y) : "l"(v)); return f;
}

// ================= K1: x = inputs@W1+b1, rope split, bias =================
// Grid: 256 blocks (BM=32), 128 threads, BN=128 (full), BK=16.
// Microtile 4m x 8n, n-pair accumulators. A stored DUPLICATED in smem
// (aD[k][2m]=(a,a)) so broadcasts are direct LDS.128 - zero packs in loop.
// Inner loop per k-step: 2 LDS.128 (a-dup) + 2 LDS.128 (b) + 16 FFMA2.
__global__ void __launch_bounds__(128) k1_gemm(
    const float* __restrict__ inp, const float* __restrict__ W1,
    const float* __restrict__ b1v, const float* __restrict__ W2,
    const float* __restrict__ b2v)
{
    __shared__ __align__(16) float sm[7296];
    // main loop: 2 x (aD[16][72]=1152 + B[16][128]=2048) = 6400 fl
    // epilogue reuse: xS[32][132]=4224 + w2t[24][128]=3072 = 7296 fl

    int t = threadIdx.x;
    int tx = t & 15, ty = t >> 4;        // 16 x 8 thread grid
    int row0 = blockIdx.x * 32;
    int bidx = row0 >> 9;
    int pos0 = row0 & 511;
    int m0 = ty * 4, n0 = tx * 4;

    int am_ = t >> 2;                    // A: row within tile (0..31)
    int akq = (t & 3) << 2;              // A: k quad within chunk

    u64 acc[4][4];                       // [m][npair]
#pragma unroll
    for (int p = 0; p < 4; p++)
#pragma unroll
        for (int j = 0; j < 4; j++) acc[p][j] = 0ULL;

    float4 apre, bpre[4];
    const float* arow = inp + (size_t)(row0 + am_) * 1024 + akq;

    // ---- chunk 0 ----
    apre = *(const float4*)(arow);
#pragma unroll
    for (int i = 0; i < 4; i++) {
        int idx = t + i * 128; int k = idx >> 5; int n4 = (idx & 31) << 2;
        bpre[i] = *(const float4*)(W1 + (size_t)k * 128 + n4);
    }
    {
        float* aD = sm;
        float* bS = sm + 1152;
        *(u64*)(aD + (akq + 0) * 72 + 2 * am_) = pk2(apre.x, apre.x);
        *(u64*)(aD + (akq + 1) * 72 + 2 * am_) = pk2(apre.y, apre.y);
        *(u64*)(aD + (akq + 2) * 72 + 2 * am_) = pk2(apre.z, apre.z);
        *(u64*)(aD + (akq + 3) * 72 + 2 * am_) = pk2(apre.w, apre.w);
#pragma unroll
        for (int i = 0; i < 4; i++) {
            int idx = t + i * 128; int k = idx >> 5; int n4 = (idx & 31) << 2;
            *(float4*)(bS + k * 128 + n4) = bpre[i];
        }
    }
    __syncthreads();

    for (int kc = 0; kc < 64; ++kc) {
        if (kc < 63) {
            int kb = (kc + 1) * 16;
            apre = *(const float4*)(arow + kb);
#pragma unroll
            for (int i = 0; i < 4; i++) {
                int idx = t + i * 128; int k = idx >> 5; int n4 = (idx & 31) << 2;
                bpre[i] = *(const float4*)(W1 + (size_t)(kb + k) * 128 + n4);
            }
        }
        const float* aD = sm + (kc & 1) * 3200;
        const float* bS = aD + 1152;
#pragma unroll
        for (int k = 0; k < 16; k++) {
            const u64* ap = (const u64*)(aD + k * 72 + 2 * m0);
            u64 a0 = ap[0], a1 = ap[1], a2 = ap[2], a3 = ap[3];
            const u64* bl = (const u64*)(bS + k * 128 + n0);
            const u64* bh = (const u64*)(bS + k * 128 + 64 + n0);
            u64 b0 = bl[0], b1 = bl[1], b2 = bh[0], b3 = bh[1];
            fma2(acc[0][0], a0, b0); fma2(acc[0][1], a0, b1);
            fma2(acc[0][2], a0, b2); fma2(acc[0][3], a0, b3);
            fma2(acc[1][0], a1, b0); fma2(acc[1][1], a1, b1);
            fma2(acc[1][2], a1, b2); fma2(acc[1][3], a1, b3);
            fma2(acc[2][0], a2, b0); fma2(acc[2][1], a2, b1);
            fma2(acc[2][2], a2, b2); fma2(acc[2][3], a2, b3);
            fma2(acc[3][0], a3, b0); fma2(acc[3][1], a3, b1);
            fma2(acc[3][2], a3, b2); fma2(acc[3][3], a3, b3);
        }
        if (kc < 63) {
            float* aDn = sm + ((kc + 1) & 1) * 3200;
            float* bSn = aDn + 1152;
            *(u64*)(aDn + (akq + 0) * 72 + 2 * am_) = pk2(apre.x, apre.x);
            *(u64*)(aDn + (akq + 1) * 72 + 2 * am_) = pk2(apre.y, apre.y);
            *(u64*)(aDn + (akq + 2) * 72 + 2 * am_) = pk2(apre.z, apre.z);
            *(u64*)(aDn + (akq + 3) * 72 + 2 * am_) = pk2(apre.w, apre.w);
#pragma unroll
            for (int i = 0; i < 4; i++) {
                int idx = t + i * 128; int k = idx >> 5; int n4 = (idx & 31) << 2;
                *(float4*)(bSn + k * 128 + n4) = bpre[i];
            }
            __syncthreads();
        }
    }

    // ---- epilogue: unpack + b1 ----
    // acc[r][j] lanes: j=0,1 -> cols n0+0..3 ; j=2,3 -> cols 64+n0+0..3
    float x[4][8];
#pragma unroll
    for (int r = 0; r < 4; r++)
#pragma unroll
        for (int j = 0; j < 4; j++) {
            float2 v = up2(acc[r][j]);
            x[r][2 * j]     = v.x;
            x[r][2 * j + 1] = v.y;
        }
    float bc[8];
#pragma unroll
    for (int j = 0; j < 4; j++) {
        bc[j]     = __ldg(b1v + n0 + j);
        bc[j + 4] = __ldg(b1v + 64 + n0 + j);
    }
#pragma unroll
    for (int r = 0; r < 4; r++)
#pragma unroll
        for (int j = 0; j < 8; j++) x[r][j] += bc[j];

    // ---- rope: thread owns channels i=tx (x cols 0..3) and i=16+tx (cols 4..7)
    {
        float invf0 = 1.0f / powf(10000.0f, (float)(2 * tx) * (1.0f / 64.0f));
        float invf1 = 1.0f / powf(10000.0f, (float)(2 * (16 + tx)) * (1.0f / 64.0f));
#pragma unroll
        for (int r = 0; r < 4; r++) {
            int pos = pos0 + m0 + r;
            size_t rb = ((size_t)bidx * 512 + pos) * 64;
            float s0, c0, s1, c1;
            sincosf((float)pos * invf0, &s0, &c0);
            sincosf((float)pos * invf1, &s1, &c1);
            float2 q0 = make_float2(x[r][0] * c0 - x[r][2] * s0, x[r][0] * s0 + x[r][2] * c0);
            float2 k0 = make_float2(x[r][1] * c0 - x[r][3] * s0, x[r][1] * s0 + x[r][3] * c0);
            float2 q1 = make_float2(x[r][4] * c1 - x[r][6] * s1, x[r][4] * s1 + x[r][6] * c1);
            float2 k1 = make_float2(x[r][5] * c1 - x[r][7] * s1, x[r][5] * s1 + x[r][7] * c1);
            *(float2*)(g_qw + rb + 2 * tx) = q0;
            *(float2*)(g_kw + rb + 2 * tx) = k0;
            *(float2*)(g_qw + rb + 2 * (16 + tx)) = q1;
            *(float2*)(g_kw + rb + 2 * (16 + tx)) = k1;
        }
    }

    // ---- bias: x @ W2 + b2, /2 ----
    __syncthreads();
    float* xS  = sm;             // [32][132]
    float* w2t = sm + 32 * 132;  // [24][128]
#pragma unroll
    for (int r = 0; r < 4; r++) {
        *(float4*)(xS + (m0 + r) * 132 + n0)      = make_float4(x[r][0], x[r][1], x[r][2], x[r][3]);
        *(float4*)(xS + (m0 + r) * 132 + 64 + n0) = make_float4(x[r][4], x[r][5], x[r][6], x[r][7]);
    }
    for (int idx = t; idx < 3072; idx += 128) {
        int j = idx >> 7, k = idx & 127;
        w2t[j * 128 + k] = __ldg(W2 + k * 24 + j);
    }
    __syncthreads();

#pragma unroll
    for (int it = 0; it < 6; ++it) {
        int idx = t + it * 128;          // 768 (j,m) pairs
        int j = idx >> 5, m = idx & 31;
        const float* xr = xS + m * 132;
        const float* wr = w2t + j * 128;
        float s = 0.f;
#pragma unroll
        for (int k = 0; k < 128; k += 4) {
            float4 xv = *(const float4*)(xr + k);
            float4 wv = *(const float4*)(wr + k);
            s += xv.x * wv.x + xv.y * wv.y + xv.z * wv.z + xv.w * wv.w;
        }
        s = (s + __ldg(b2v + j)) * 0.5f;
        int pos = pos0 + m;
        int h = j >> 1;
        float* dst = (j & 1) ? g_bk : g_bq;
        dst[((size_t)bidx * 12 + h) * 512 + pos] = s;
    }
}

// ================= K2: qk + per-head epilogue + masks =================
// Grid (8 n-tiles, 8 m-tiles, 16 batches), 256 threads.
// Tile: 64m x 64n; microtile 4m x 4n. qk computed once (f32x2), 12-head fanout.
__global__ void __launch_bounds__(256) k2_out(const float* __restrict__ am,
                                              float* __restrict__ out)
{
    __shared__ __align__(16) float q_s[64 * 68];
    __shared__ __align__(16) float kT[64 * 64];
    __shared__ __align__(16) float bq_s[12 * 64];
    __shared__ __align__(16) float bk_s[12 * 64];
    __shared__ float amn_s[64];
    __shared__ float amm_s[64];

    int t = threadIdx.x;
    int b = blockIdx.z;
    int m0g = blockIdx.y * 64, n0g = blockIdx.x * 64;

#pragma unroll
    for (int i = 0; i < 4; i++) {
        int idx = t + i * 256;
        int row = idx >> 4, c = (idx & 15) << 2;
        *(float4*)(q_s + row * 68 + c) =
            *(const float4*)(g_qw + ((size_t)(b * 512 + m0g + row)) * 64 + c);
    }
    {
        int n = t & 63, kq = (t >> 6) << 4;
        const float* src = g_kw + ((size_t)(b * 512 + n0g + n)) * 64 + kq;
#pragma unroll
        for (int j = 0; j < 4; j++) {
            float4 v = *(const float4*)(src + j * 4);
            int kk = kq + j * 4;
            kT[(kk + 0) * 64 + n] = v.x;
            kT[(kk + 1) * 64 + n] = v.y;
            kT[(kk + 2) * 64 + n] = v.z;
            kT[(kk + 3) * 64 + n] = v.w;
        }
    }
#pragma unroll
    for (int i = 0; i < 3; i++) {
        int idx = t + i * 256;           // 768 entries each
        int h = idx >> 6, x = idx & 63;
        bq_s[idx] = g_bq[((size_t)b * 12 + h) * 512 + n0g + x];
        bk_s[idx] = g_bk[((size_t)b * 12 + h) * 512 + m0g + x];
    }
    if (t < 64)        amn_s[t]      = am[b * 512 + n0g + t];
    else if (t < 128)  amm_s[t - 64] = am[b * 512 + m0g + (t - 64)];
    __syncthreads();

    int tx = t & 15, ty = t >> 4;
    int n0 = tx * 4, m0 = ty * 4;

    // f32x2 qk accumulation: acc[m][npair]
    u64 acc[4][2];
#pragma unroll
    for (int r = 0; r < 4; r++) { acc[r][0] = 0ULL; acc[r][1] = 0ULL; }

#pragma unroll
    for (int k = 0; k < 64; k += 4) {
        float4 qr[4];
#pragma unroll
        for (int r = 0; r < 4; r++)
            qr[r] = *(const float4*)(q_s + (m0 + r) * 68 + k);
#pragma unroll
        for (int kk = 0; kk < 4; kk++) {
            const u64* kv = (const u64*)(kT + (k + kk) * 64 + n0);
            u64 k01 = kv[0], k23 = kv[1];
#pragma unroll
            for (int r = 0; r < 4; r++) {
                float qv = (kk == 0) ? qr[r].x : (kk == 1) ? qr[r].y
                         : (kk == 2) ? qr[r].z : qr[r].w;
                u64 qp = pk2(qv, qv);
                fma2(acc[r][0], k01, qp);
                fma2(acc[r][1], k23, qp);
            }
        }
    }

    float4 amn4 = *(const float4*)(amn_s + n0);
    float amn[4] = {amn4.x, amn4.y, amn4.z, amn4.w};
    int gn = n0g + n0;

    // pre = qk*0.125 - at - tr  (hoisted out of head loop; exact vs ref)
    u64 pre[4][2];
#pragma unroll
    for (int r = 0; r < 4; r++) {
        float am_m = amm_s[m0 + r];
        int gm = m0g + m0 + r;
        float2 vA = up2(acc[r][0]), vB = up2(acc[r][1]);
        float p[4] = {vA.x, vA.y, vB.x, vB.y};
        float pr[4];
#pragma unroll
        for (int j = 0; j < 4; j++) {
            float at = (1.0f - amn[j] * am_m) * INF_F;
            float tr = (gn + j < gm) ? INF_F : 0.f;
            pr[j] = p[j] * 0.125f - at - tr;
        }
        pre[r][0] = pk2(pr[0], pr[1]);
        pre[r][1] = pk2(pr[2], pr[3]);
    }

    float* obase = out + (((size_t)b * 12 * 512 + m0g + m0) * 512 + gn);
#pragma unroll
    for (int h = 0; h < 12; ++h) {
        const u64* bqp = (const u64*)(bq_s + h * 64 + n0);
        u64 bqa = bqp[0], bqb = bqp[1];
        float4 bk4 = *(const float4*)(bk_s + h * 64 + m0);
        float* oh = obase + (size_t)h * 512 * 512;
#pragma unroll
        for (int r = 0; r < 4; r++) {
            float bkv = (r == 0) ? bk4.x : (r == 1) ? bk4.y : (r == 2) ? bk4.z : bk4.w;
            u64 bkp = pk2(bkv, bkv);
            u64 wa = add2(add2(pre[r][0], bqa), bkp);
            u64 wb = add2(add2(pre[r][1], bqb), bkp);
            float2 lo = up2(wa), hi = up2(wb);
            __stcs((float4*)(oh + (size_t)r * 512), make_float4(lo.x, lo.y, hi.x, hi.y));
        }
    }
}

// ================= launch =================
extern "C" void kernel_launch(void* const* d_in, const int* in_sizes, int n_in,
                              void* d_out, int out_size)
{
    const float* inp = (const float*)d_in[0];
    const float* am  = (const float*)d_in[1];
    const float* W1  = (const float*)d_in[2];
    const float* b1  = (const float*)d_in[3];
    const float* W2  = (const float*)d_in[4];
    const float* b2  = (const float*)d_in[5];
    float* out = (float*)d_out;

    k1_gemm<<<256, 128>>>(inp, W1, b1, W2, b2);
    k2_out<<<dim3(8, 8, 16), 256>>>(am, out);
}

// round 9
// speedup vs baseline: 1.1522x; 1.1293x over previous
#include <cuda_runtime.h>
#include <math.h>

#define INF_F 1000000000000.0f

typedef unsigned long long u64;

// ---------------- scratch (no cudaMalloc allowed) ----------------
__device__ float g_qw[16 * 512 * 64];    // rope'd q
__device__ float g_kw[16 * 512 * 64];    // rope'd k
__device__ float g_bq[16 * 12 * 512];    // bias[:,0::2]/2  (indexed by n)
__device__ float g_bk[16 * 12 * 512];    // bias[:,1::2]/2  (indexed by m)

// ---------------- f32x2 packed helpers (Blackwell FFMA2) ----------
__device__ __forceinline__ u64 pk2(float lo, float hi) {
    u64 r; asm("mov.b64 %0,{%1,%2};" : "=l"(r) : "f"(lo), "f"(hi)); return r;
}
__device__ __forceinline__ void fma2(u64 &c, u64 a, u64 b) {
    asm("fma.rn.f32x2 %0,%1,%2,%0;" : "+l"(c) : "l"(a), "l"(b));
}
__device__ __forceinline__ u64 add2(u64 a, u64 b) {
    u64 d; asm("add.rn.f32x2 %0,%1,%2;" : "=l"(d) : "l"(a), "l"(b)); return d;
}
__device__ __forceinline__ float2 up2(u64 v) {
    float2 f; asm("mov.b64 {%0,%1},%2;" : "=f"(f.x), "=f"(f.y) : "l"(v)); return f;
}

// ================= nop: parity shifter so ncu (-s 5) lands on k1 ==========
__global__ void k_nop() {}

// ================= K1: x = inputs@W1+b1, rope split, bias =================
// (R6 version - measured best K1.)
// Grid: 256 blocks (BM=32), 128 threads, BN=128 (full), BK=16.
// Microtile 4m x 8n via FFMA2 on n-pairs (b loaded as u64 directly from smem,
// a broadcast-packed: 4 MOVs per k-step). Double-buffered, 1 sync/chunk.
// Rope sin/cos table per-block in spare smem, overlapped with chunk-0 loads.
__global__ void __launch_bounds__(128) k1_gemm(
    const float* __restrict__ inp, const float* __restrict__ W1,
    const float* __restrict__ b1v, const float* __restrict__ W2,
    const float* __restrict__ b2v)
{
    __shared__ __align__(16) float sm[7296];
    // main loop: 2 x (A[16][36]=576 + B[16][128]=2048) = 5248 fl
    // sin/cos table: [5248..7296) = 1024+1024 fl (local pos 0..31 x i 0..31)
    // epilogue reuse: xS[32][132]=4224 + w2t[24][128]=3072 = 7296 fl
    float* sinS = sm + 5248;
    float* cosS = sm + 6272;

    int t = threadIdx.x;
    int tx = t & 15, ty = t >> 4;        // 16 x 8 thread grid
    int row0 = blockIdx.x * 32;
    int bidx = row0 >> 9;
    int pos0 = row0 & 511;
    int m0 = ty * 4, n0 = tx * 4;

    int am_ = t >> 2;                    // A: row within tile (0..31)
    int akq = (t & 3) << 2;              // A: k quad within chunk

    u64 acc[4][4];                       // [m][npair]
#pragma unroll
    for (int p = 0; p < 4; p++)
#pragma unroll
        for (int j = 0; j < 4; j++) acc[p][j] = 0ULL;

    float4 apre, bpre[4];
    const float* arow = inp + (size_t)(row0 + am_) * 1024 + akq;

    // ---- issue chunk-0 global loads first (latency cover for sincos below)
    apre = *(const float4*)(arow);
#pragma unroll
    for (int i = 0; i < 4; i++) {
        int idx = t + i * 128; int k = idx >> 5; int n4 = (idx & 31) << 2;
        bpre[i] = *(const float4*)(W1 + (size_t)k * 128 + n4);
    }

    // ---- rope tables for this block's 32 positions (exact: powf + sincosf)
    {
        int i = t & 31;                  // rope channel 0..31
        int pr0 = (t >> 5) * 8;          // 8 local positions per thread
        float e = (float)(2 * i) * (1.0f / 64.0f);
        float invf = 1.0f / powf(10000.0f, e);
#pragma unroll
        for (int r = 0; r < 8; r++) {
            int pl = pr0 + r;
            float fr = (float)(pos0 + pl) * invf;
            float s, c;
            sincosf(fr, &s, &c);
            sinS[pl * 32 + i] = s;
            cosS[pl * 32 + i] = c;
        }
    }

    {
        float* aT = sm;
        float* bS = sm + 576;
        aT[(akq + 0) * 36 + am_] = apre.x;
        aT[(akq + 1) * 36 + am_] = apre.y;
        aT[(akq + 2) * 36 + am_] = apre.z;
        aT[(akq + 3) * 36 + am_] = apre.w;
#pragma unroll
        for (int i = 0; i < 4; i++) {
            int idx = t + i * 128; int k = idx >> 5; int n4 = (idx & 31) << 2;
            *(float4*)(bS + k * 128 + n4) = bpre[i];
        }
    }
    __syncthreads();

    for (int kc = 0; kc < 64; ++kc) {
        if (kc < 63) {
            int kb = (kc + 1) * 16;
            apre = *(const float4*)(arow + kb);
#pragma unroll
            for (int i = 0; i < 4; i++) {
                int idx = t + i * 128; int k = idx >> 5; int n4 = (idx & 31) << 2;
                bpre[i] = *(const float4*)(W1 + (size_t)(kb + k) * 128 + n4);
            }
        }
        const float* aT = sm + (kc & 1) * 2624;
        const float* bS = aT + 576;
#pragma unroll
        for (int k = 0; k < 16; k++) {
            float4 a = *(const float4*)(aT + k * 36 + m0);
            const u64* bl = (const u64*)(bS + k * 128 + n0);
            const u64* bh = (const u64*)(bS + k * 128 + 64 + n0);
            u64 b0 = bl[0], b1 = bl[1], b2 = bh[0], b3 = bh[1];
            u64 a0 = pk2(a.x, a.x), a1 = pk2(a.y, a.y);
            u64 a2 = pk2(a.z, a.z), a3 = pk2(a.w, a.w);
            fma2(acc[0][0], a0, b0); fma2(acc[0][1], a0, b1);
            fma2(acc[0][2], a0, b2); fma2(acc[0][3], a0, b3);
            fma2(acc[1][0], a1, b0); fma2(acc[1][1], a1, b1);
            fma2(acc[1][2], a1, b2); fma2(acc[1][3], a1, b3);
            fma2(acc[2][0], a2, b0); fma2(acc[2][1], a2, b1);
            fma2(acc[2][2], a2, b2); fma2(acc[2][3], a2, b3);
            fma2(acc[3][0], a3, b0); fma2(acc[3][1], a3, b1);
            fma2(acc[3][2], a3, b2); fma2(acc[3][3], a3, b3);
        }
        if (kc < 63) {
            float* aTn = sm + ((kc + 1) & 1) * 2624;
            float* bSn = aTn + 576;
            aTn[(akq + 0) * 36 + am_] = apre.x;
            aTn[(akq + 1) * 36 + am_] = apre.y;
            aTn[(akq + 2) * 36 + am_] = apre.z;
            aTn[(akq + 3) * 36 + am_] = apre.w;
#pragma unroll
            for (int i = 0; i < 4; i++) {
                int idx = t + i * 128; int k = idx >> 5; int n4 = (idx & 31) << 2;
                *(float4*)(bSn + k * 128 + n4) = bpre[i];
            }
            __syncthreads();
        }
    }

    // ---- epilogue: unpack + b1 ----
    // acc[r][j] lanes: j=0,1 -> cols n0+0..3 ; j=2,3 -> cols 64+n0+0..3
    float x[4][8];
#pragma unroll
    for (int r = 0; r < 4; r++)
#pragma unroll
        for (int j = 0; j < 4; j++) {
            float2 v = up2(acc[r][j]);
            x[r][2 * j]     = v.x;
            x[r][2 * j + 1] = v.y;
        }
    float bc[8];
#pragma unroll
    for (int j = 0; j < 4; j++) {
        bc[j]     = __ldg(b1v + n0 + j);
        bc[j + 4] = __ldg(b1v + 64 + n0 + j);
    }
#pragma unroll
    for (int r = 0; r < 4; r++)
#pragma unroll
        for (int j = 0; j < 8; j++) x[r][j] += bc[j];

    // ---- rope: cols (4tx..4tx+3) hold full q/k rope pairs for i=tx; +64 for i=16+tx
#pragma unroll
    for (int r = 0; r < 4; r++) {
        int pl = m0 + r;                 // local position 0..31
        int pos = pos0 + pl;
        size_t rb = ((size_t)bidx * 512 + pos) * 64;
        {
            int i = tx;
            float s = sinS[pl * 32 + i], c = cosS[pl * 32 + i];
            float2 q = make_float2(x[r][0] * c - x[r][2] * s, x[r][0] * s + x[r][2] * c);
            float2 kk = make_float2(x[r][1] * c - x[r][3] * s, x[r][1] * s + x[r][3] * c);
            *(float2*)(g_qw + rb + 2 * i) = q;
            *(float2*)(g_kw + rb + 2 * i) = kk;
        }
        {
            int i = 16 + tx;
            float s = sinS[pl * 32 + i], c = cosS[pl * 32 + i];
            float2 q = make_float2(x[r][4] * c - x[r][6] * s, x[r][4] * s + x[r][6] * c);
            float2 kk = make_float2(x[r][5] * c - x[r][7] * s, x[r][5] * s + x[r][7] * c);
            *(float2*)(g_qw + rb + 2 * i) = q;
            *(float2*)(g_kw + rb + 2 * i) = kk;
        }
    }

    // ---- bias: x @ W2 + b2, /2 ----
    __syncthreads();
    float* xS  = sm;             // [32][132]
    float* w2t = sm + 32 * 132;  // [24][128]  (overwrites sin/cos table - done)
#pragma unroll
    for (int r = 0; r < 4; r++) {
        *(float4*)(xS + (m0 + r) * 132 + n0)      = make_float4(x[r][0], x[r][1], x[r][2], x[r][3]);
        *(float4*)(xS + (m0 + r) * 132 + 64 + n0) = make_float4(x[r][4], x[r][5], x[r][6], x[r][7]);
    }
    for (int idx = t; idx < 3072; idx += 128) {
        int j = idx >> 7, k = idx & 127;
        w2t[j * 128 + k] = __ldg(W2 + k * 24 + j);
    }
    __syncthreads();

#pragma unroll
    for (int it = 0; it < 6; ++it) {
        int idx = t + it * 128;          // 768 (j,m) pairs
        int j = idx >> 5, m = idx & 31;
        const float* xr = xS + m * 132;
        const float* wr = w2t + j * 128;
        float s = 0.f;
#pragma unroll
        for (int k = 0; k < 128; k += 4) {
            float4 xv = *(const float4*)(xr + k);
            float4 wv = *(const float4*)(wr + k);
            s += xv.x * wv.x + xv.y * wv.y + xv.z * wv.z + xv.w * wv.w;
        }
        s = (s + __ldg(b2v + j)) * 0.5f;
        int pos = pos0 + m;
        int h = j >> 1;
        float* dst = (j & 1) ? g_bk : g_bq;
        dst[((size_t)bidx * 12 + h) * 512 + pos] = s;
    }
}

// ================= K2: qk + per-head epilogue + masks =================
// (R8 version - measured best K2: 42.7us.)
// Grid (8 n-tiles, 8 m-tiles, 16 batches), 256 threads.
// Tile: 64m x 64n; microtile 4m x 4n. qk computed once (f32x2), 12-head fanout.
__global__ void __launch_bounds__(256) k2_out(const float* __restrict__ am,
                                              float* __restrict__ out)
{
    __shared__ __align__(16) float q_s[64 * 68];
    __shared__ __align__(16) float kT[64 * 64];
    __shared__ __align__(16) float bq_s[12 * 64];
    __shared__ __align__(16) float bk_s[12 * 64];
    __shared__ float amn_s[64];
    __shared__ float amm_s[64];

    int t = threadIdx.x;
    int b = blockIdx.z;
    int m0g = blockIdx.y * 64, n0g = blockIdx.x * 64;

#pragma unroll
    for (int i = 0; i < 4; i++) {
        int idx = t + i * 256;
        int row = idx >> 4, c = (idx & 15) << 2;
        *(float4*)(q_s + row * 68 + c) =
            *(const float4*)(g_qw + ((size_t)(b * 512 + m0g + row)) * 64 + c);
    }
    {
        int n = t & 63, kq = (t >> 6) << 4;
        const float* src = g_kw + ((size_t)(b * 512 + n0g + n)) * 64 + kq;
#pragma unroll
        for (int j = 0; j < 4; j++) {
            float4 v = *(const float4*)(src + j * 4);
            int kk = kq + j * 4;
            kT[(kk + 0) * 64 + n] = v.x;
            kT[(kk + 1) * 64 + n] = v.y;
            kT[(kk + 2) * 64 + n] = v.z;
            kT[(kk + 3) * 64 + n] = v.w;
        }
    }
#pragma unroll
    for (int i = 0; i < 3; i++) {
        int idx = t + i * 256;           // 768 entries each
        int h = idx >> 6, x = idx & 63;
        bq_s[idx] = g_bq[((size_t)b * 12 + h) * 512 + n0g + x];
        bk_s[idx] = g_bk[((size_t)b * 12 + h) * 512 + m0g + x];
    }
    if (t < 64)        amn_s[t]      = am[b * 512 + n0g + t];
    else if (t < 128)  amm_s[t - 64] = am[b * 512 + m0g + (t - 64)];
    __syncthreads();

    int tx = t & 15, ty = t >> 4;
    int n0 = tx * 4, m0 = ty * 4;

    // f32x2 qk accumulation: acc[m][npair]
    u64 acc[4][2];
#pragma unroll
    for (int r = 0; r < 4; r++) { acc[r][0] = 0ULL; acc[r][1] = 0ULL; }

#pragma unroll
    for (int k = 0; k < 64; k += 4) {
        float4 qr[4];
#pragma unroll
        for (int r = 0; r < 4; r++)
            qr[r] = *(const float4*)(q_s + (m0 + r) * 68 + k);
#pragma unroll
        for (int kk = 0; kk < 4; kk++) {
            const u64* kv = (const u64*)(kT + (k + kk) * 64 + n0);
            u64 k01 = kv[0], k23 = kv[1];
#pragma unroll
            for (int r = 0; r < 4; r++) {
                float qv = (kk == 0) ? qr[r].x : (kk == 1) ? qr[r].y
                         : (kk == 2) ? qr[r].z : qr[r].w;
                u64 qp = pk2(qv, qv);
                fma2(acc[r][0], k01, qp);
                fma2(acc[r][1], k23, qp);
            }
        }
    }

    float4 amn4 = *(const float4*)(amn_s + n0);
    float amn[4] = {amn4.x, amn4.y, amn4.z, amn4.w};
    int gn = n0g + n0;

    // pre = qk*0.125 - at - tr  (hoisted out of head loop; exact vs ref)
    u64 pre[4][2];
#pragma unroll
    for (int r = 0; r < 4; r++) {
        float am_m = amm_s[m0 + r];
        int gm = m0g + m0 + r;
        float2 vA = up2(acc[r][0]), vB = up2(acc[r][1]);
        float p[4] = {vA.x, vA.y, vB.x, vB.y};
        float pr[4];
#pragma unroll
        for (int j = 0; j < 4; j++) {
            float at = (1.0f - amn[j] * am_m) * INF_F;
            float tr = (gn + j < gm) ? INF_F : 0.f;
            pr[j] = p[j] * 0.125f - at - tr;
        }
        pre[r][0] = pk2(pr[0], pr[1]);
        pre[r][1] = pk2(pr[2], pr[3]);
    }

    float* obase = out + (((size_t)b * 12 * 512 + m0g + m0) * 512 + gn);
#pragma unroll
    for (int h = 0; h < 12; ++h) {
        const u64* bqp = (const u64*)(bq_s + h * 64 + n0);
        u64 bqa = bqp[0], bqb = bqp[1];
        float4 bk4 = *(const float4*)(bk_s + h * 64 + m0);
        float* oh = obase + (size_t)h * 512 * 512;
#pragma unroll
        for (int r = 0; r < 4; r++) {
            float bkv = (r == 0) ? bk4.x : (r == 1) ? bk4.y : (r == 2) ? bk4.z : bk4.w;
            u64 bkp = pk2(bkv, bkv);
            u64 wa = add2(add2(pre[r][0], bqa), bkp);
            u64 wb = add2(add2(pre[r][1], bqb), bkp);
            float2 lo = up2(wa), hi = up2(wb);
            __stcs((float4*)(oh + (size_t)r * 512), make_float4(lo.x, lo.y, hi.x, hi.y));
        }
    }
}

// ================= launch =================
// Sequence [nop, k1, k2, nop] (period 4) so ncu's skip-5 capture lands on
// launch index 5 === 1 (mod 4) = k1_gemm, finally profiling K1.
extern "C" void kernel_launch(void* const* d_in, const int* in_sizes, int n_in,
                              void* d_out, int out_size)
{
    const float* inp = (const float*)d_in[0];
    const float* am  = (const float*)d_in[1];
    const float* W1  = (const float*)d_in[2];
    const float* b1  = (const float*)d_in[3];
    const float* W2  = (const float*)d_in[4];
    const float* b2  = (const float*)d_in[5];
    float* out = (float*)d_out;

    k_nop<<<1, 32>>>();
    k1_gemm<<<256, 128>>>(inp, W1, b1, W2, b2);
    k2_out<<<dim3(8, 8, 16), 256>>>(am, out);
    k_nop<<<1, 32>>>();
}